// round 9
// baseline (speedup 1.0000x reference)
#include <cuda_runtime.h>
#include <cuda_bf16.h>
#include <cstdint>

// Problem constants
static constexpr int BATCH = 8;
static constexpr int SEQ   = 2048;
static constexpr int DIM   = 768;
static constexpr long long BSD = (long long)BATCH * SEQ * DIM;

// Scratch (device globals: allocation-free per harness rules). 16B-aligned for cp.async.
__device__ __align__(16) float g_xtf[BATCH * SEQ * DIM];      // x, tf32-rounded
__device__ __align__(16) float g_wtf[3 * DIM * DIM];          // w, tf32-rounded
__device__ __align__(16) float g_qkv[3 * BATCH * SEQ * DIM];  // q|k|v (tf32-rounded)
__device__ __align__(16) float g_s[BATCH * SEQ * SEQ];        // scores / attn

__device__ __forceinline__ uint32_t f2tf32(float f) {
    uint32_t u;
    asm volatile("cvt.rna.tf32.f32 %0, %1;" : "=r"(u) : "f"(f));
    return u;
}
__device__ __forceinline__ float rna(float f) { return __uint_as_float(f2tf32(f)); }

__device__ __forceinline__ void mma_tf32(
    float& c0, float& c1, float& c2, float& c3,
    uint32_t a0, uint32_t a1, uint32_t a2, uint32_t a3,
    uint32_t b0, uint32_t b1)
{
    asm volatile(
        "mma.sync.aligned.m16n8k8.row.col.f32.tf32.tf32.f32 "
        "{%0,%1,%2,%3}, {%4,%5,%6,%7}, {%8,%9}, {%0,%1,%2,%3};\n"
        : "+f"(c0), "+f"(c1), "+f"(c2), "+f"(c3)
        : "r"(a0), "r"(a1), "r"(a2), "r"(a3), "r"(b0), "r"(b1));
}

__device__ __forceinline__ void cp16(void* smem_dst, const void* gsrc) {
    uint32_t sa = (uint32_t)__cvta_generic_to_shared(smem_dst);
    asm volatile("cp.async.cg.shared.global [%0], [%1], 16;\n" :: "r"(sa), "l"(gsrc));
}

// ---------------------------------------------------------------------------
// tf32 tensor-core GEMM, 3-stage cp.async pipeline: C = alpha * A @ B(^T)
// Inputs MUST already be tf32-rounded fp32 (no CVT in consumer loop).
//   A: [M,K] row-major; B: NN -> [K,N], NT -> [N,K]; C: [M,N]
// M,N % 128 == 0; K % 32 == 0.
// CTA 128x128x32, 8 warps (2x4), warp tile 64x32, mma m16n8k8; 2 CTAs/SM.
//   As  [m][k]  stride 36 ; BsNN [k][n] stride 136 ; BsNT [n][k] stride 36
// R9: ONE __syncthreads per k-tile. Order: wait(1) -> sync -> load(t+2) ->
// commit -> MMA(t). Safety: load at iter t writes slot (t+2)%3 == (t-1)%3;
// every warp's MMA(t-1) precedes iter-t's collective sync in program order,
// so the single sync orders buffer reuse. wait_group 1 is correct because
// tile t+2's commit happens after the wait (outstanding at wait = tile t+1).
// ---------------------------------------------------------------------------
#define BM 128
#define BN 128
#define BK 32
#define STAGES 3

static constexpr int AS_STRIDE = BK + 4;                 // 36
static constexpr int ASZ = BM * AS_STRIDE;               // floats per A stage
template <bool BT> struct BDims {
    static constexpr int STRIDE = BT ? (BK + 4) : (BN + 8);
    static constexpr int SZ     = BT ? (BN * (BK + 4)) : (BK * (BN + 8));
};

template <bool BT, bool ROUND>
__global__ __launch_bounds__(256, 2) void mma_gemm(
    const float* __restrict__ Ab, const float* __restrict__ Bb,
    float* __restrict__ Cb,
    int M, int N, int K,
    long long sA, long long sB, long long sC, float alpha)
{
    constexpr int BS_STRIDE = BDims<BT>::STRIDE;
    constexpr int BSZ       = BDims<BT>::SZ;

    const float* A = Ab + (long long)blockIdx.z * sA;
    const float* B = Bb + (long long)blockIdx.z * sB;
    float*       C = Cb + (long long)blockIdx.z * sC;

    extern __shared__ float smem[];
    float* AsBase = smem;
    float* BsBase = smem + STAGES * ASZ;

    const int tid  = threadIdx.x;
    const int warp = tid >> 5;
    const int lane = tid & 31;
    const int gid  = lane >> 2;   // 0..7
    const int tig  = lane & 3;    // 0..3
    const int wm   = (warp >> 2) * 64;
    const int wn   = (warp & 3) * 32;
    const int row0 = blockIdx.y * BM;
    const int col0 = blockIdx.x * BN;

    float c[4][4][4];
#pragma unroll
    for (int i = 0; i < 4; i++)
#pragma unroll
        for (int j = 0; j < 4; j++)
#pragma unroll
            for (int r = 0; r < 4; r++) c[i][j][r] = 0.f;

    const int aR = tid >> 3;            // 0..31 (+32/pass), 16B along k
    const int aC = (tid & 7) * 4;
    const int bR = tid >> 5;            // 0..7 (+8/pass), 16B along n (NN)
    const int bC = (tid & 31) * 4;

    auto load_tile = [&](int stage, int kt) {
        float* As = AsBase + stage * ASZ;
        float* Bs = BsBase + stage * BSZ;
#pragma unroll
        for (int p = 0; p < 4; p++) {
            int r = aR + p * 32;
            cp16(&As[r * AS_STRIDE + aC], A + (long long)(row0 + r) * K + kt + aC);
        }
        if (BT) {
#pragma unroll
            for (int p = 0; p < 4; p++) {
                int r = aR + p * 32;
                cp16(&Bs[r * BS_STRIDE + aC], B + (long long)(col0 + r) * K + kt + aC);
            }
        } else {
#pragma unroll
            for (int p = 0; p < 4; p++) {
                int r = bR + p * 8;
                cp16(&Bs[r * BS_STRIDE + bC], B + (long long)(kt + r) * N + col0 + bC);
            }
        }
    };

    const int T = K / BK;
    load_tile(0, 0);
    asm volatile("cp.async.commit_group;\n");
    load_tile(1, BK);
    asm volatile("cp.async.commit_group;\n");

    for (int t = 0; t < T; t++) {
        asm volatile("cp.async.wait_group 1;\n");   // tile t complete
        __syncthreads();   // data visible to all warps; orders MMA(t-1) vs load below

        int nt = t + 2;
        if (nt < T) load_tile(nt % STAGES, nt * BK);
        asm volatile("cp.async.commit_group;\n");

        const uint32_t* As = (const uint32_t*)(AsBase + (t % STAGES) * ASZ);
        const uint32_t* Bs = (const uint32_t*)(BsBase + (t % STAGES) * BSZ);

#pragma unroll
        for (int ks = 0; ks < BK; ks += 8) {
            uint32_t a[4][4];
#pragma unroll
            for (int i = 0; i < 4; i++) {
                int m = wm + 16 * i + gid;
                a[i][0] = As[m * AS_STRIDE + ks + tig];
                a[i][1] = As[(m + 8) * AS_STRIDE + ks + tig];
                a[i][2] = As[m * AS_STRIDE + ks + tig + 4];
                a[i][3] = As[(m + 8) * AS_STRIDE + ks + tig + 4];
            }
            uint32_t b[4][2];
#pragma unroll
            for (int j = 0; j < 4; j++) {
                int n = wn + 8 * j + gid;
                if (BT) {
                    b[j][0] = Bs[n * BS_STRIDE + ks + tig];
                    b[j][1] = Bs[n * BS_STRIDE + ks + tig + 4];
                } else {
                    b[j][0] = Bs[(ks + tig) * BS_STRIDE + n];
                    b[j][1] = Bs[(ks + tig + 4) * BS_STRIDE + n];
                }
            }
#pragma unroll
            for (int i = 0; i < 4; i++)
#pragma unroll
                for (int j = 0; j < 4; j++)
                    mma_tf32(c[i][j][0], c[i][j][1], c[i][j][2], c[i][j][3],
                             a[i][0], a[i][1], a[i][2], a[i][3],
                             b[j][0], b[j][1]);
        }
        // no trailing sync: next iteration's sync provides the ordering
    }

#pragma unroll
    for (int i = 0; i < 4; i++) {
        int rowA = row0 + wm + 16 * i + gid;
#pragma unroll
        for (int j = 0; j < 4; j++) {
            int col = col0 + wn + 8 * j + 2 * tig;
            float f0 = c[i][j][0] * alpha, f1 = c[i][j][1] * alpha;
            float f2 = c[i][j][2] * alpha, f3 = c[i][j][3] * alpha;
            if (ROUND) { f0 = rna(f0); f1 = rna(f1); f2 = rna(f2); f3 = rna(f3); }
            *(float2*)(C + (long long)rowA * N + col) = make_float2(f0, f1);
            *(float2*)(C + (long long)(rowA + 8) * N + col) = make_float2(f2, f3);
        }
    }
}

// ---------------------------------------------------------------------------
// Elementwise tf32 rounding (prep)
// ---------------------------------------------------------------------------
__global__ __launch_bounds__(256) void cvt_rna_kernel(
    const float* __restrict__ in, float* __restrict__ out)
{
    int i = (blockIdx.x * 256 + threadIdx.x) * 4;
    float4 v = *(const float4*)(in + i);
    v.x = rna(v.x); v.y = rna(v.y); v.z = rna(v.z); v.w = rna(v.w);
    *(float4*)(out + i) = v;
}

// ---------------------------------------------------------------------------
// Row softmax over 2048 columns; float4 I/O; writes tf32-rounded probabilities
// ---------------------------------------------------------------------------
__global__ __launch_bounds__(256) void softmax2048(float* __restrict__ S)
{
    float4* row4 = (float4*)(S + (long long)blockIdx.x * SEQ);
    const int tid = threadIdx.x;

    float4 va = row4[tid];
    float4 vb = row4[tid + 256];
    float x[8] = {va.x, va.y, va.z, va.w, vb.x, vb.y, vb.z, vb.w};

    float m = x[0];
#pragma unroll
    for (int i = 1; i < 8; i++) m = fmaxf(m, x[i]);
#pragma unroll
    for (int o = 16; o > 0; o >>= 1)
        m = fmaxf(m, __shfl_xor_sync(0xffffffffu, m, o));

    __shared__ float red[8];
    if ((tid & 31) == 0) red[tid >> 5] = m;
    __syncthreads();
    float mAll = red[0];
#pragma unroll
    for (int i = 1; i < 8; i++) mAll = fmaxf(mAll, red[i]);
    __syncthreads();

    float s = 0.f;
#pragma unroll
    for (int i = 0; i < 8; i++) {
        x[i] = __expf(x[i] - mAll);
        s += x[i];
    }
#pragma unroll
    for (int o = 16; o > 0; o >>= 1)
        s += __shfl_xor_sync(0xffffffffu, s, o);
    if ((tid & 31) == 0) red[tid >> 5] = s;
    __syncthreads();
    float tot = 0.f;
#pragma unroll
    for (int i = 0; i < 8; i++) tot += red[i];

    const float inv = 1.f / tot;
#pragma unroll
    for (int i = 0; i < 8; i++) x[i] = rna(x[i] * inv);
    row4[tid]       = make_float4(x[0], x[1], x[2], x[3]);
    row4[tid + 256] = make_float4(x[4], x[5], x[6], x[7]);
}

// ---------------------------------------------------------------------------
// Launch
// ---------------------------------------------------------------------------
extern "C" void kernel_launch(void* const* d_in, const int* in_sizes, int n_in,
                              void* d_out, int out_size)
{
    const float* x = (const float*)d_in[0];   // [8, 2048, 768]
    const float* w = (const float*)d_in[1];   // [3, 768, 768]
    float* out     = (float*)d_out;           // [8, 2048, 768]

    float *xtf, *wtf, *qkv, *sc;
    cudaGetSymbolAddress((void**)&xtf, g_xtf);
    cudaGetSymbolAddress((void**)&wtf, g_wtf);
    cudaGetSymbolAddress((void**)&qkv, g_qkv);
    cudaGetSymbolAddress((void**)&sc,  g_s);

    const float INV_SCALE = 0.125f;  // 1 / sqrt(64)

    constexpr int SMEM_NN = STAGES * (ASZ + BDims<false>::SZ) * 4;  // 107,520 B
    constexpr int SMEM_NT = STAGES * (ASZ + BDims<true>::SZ) * 4;   // 110,592 B

    cudaFuncSetAttribute(mma_gemm<false, true>,
                         cudaFuncAttributeMaxDynamicSharedMemorySize, SMEM_NN);
    cudaFuncSetAttribute(mma_gemm<false, false>,
                         cudaFuncAttributeMaxDynamicSharedMemorySize, SMEM_NN);
    cudaFuncSetAttribute(mma_gemm<true, false>,
                         cudaFuncAttributeMaxDynamicSharedMemorySize, SMEM_NT);

    // 0) Pre-round x and w to tf32 (no CVT in GEMM hot loops)
    cvt_rna_kernel<<<(BATCH * SEQ * DIM) / 1024, 256>>>(x, xtf);
    cvt_rna_kernel<<<(3 * DIM * DIM) / 1024, 256>>>(w, wtf);

    // 1) QKV projection: [16384,768] @ [768,768] per weight slice (z=3);
    //    outputs rounded to tf32 so stages 2/4 need no CVT.
    {
        dim3 grid(DIM / BN, (BATCH * SEQ) / BM, 3);
        mma_gemm<false, true><<<grid, 256, SMEM_NN>>>(xtf, wtf, qkv,
                                       BATCH * SEQ, DIM, DIM,
                                       0LL, (long long)DIM * DIM, BSD, 1.0f);
    }

    // 2) scores = Q @ K^T / 8  (batched over 8); output stays fp32 for softmax
    {
        dim3 grid(SEQ / BN, SEQ / BM, BATCH);
        mma_gemm<true, false><<<grid, 256, SMEM_NT>>>(qkv, qkv + BSD, sc,
                                      SEQ, SEQ, DIM,
                                      (long long)SEQ * DIM, (long long)SEQ * DIM,
                                      (long long)SEQ * SEQ, INV_SCALE);
    }

    // 3) softmax over last dim; writes tf32-rounded attn
    softmax2048<<<BATCH * SEQ, 256>>>(sc);

    // 4) out = attn @ V  (batched over 8)
    {
        dim3 grid(DIM / BN, SEQ / BM, BATCH);
        mma_gemm<false, false><<<grid, 256, SMEM_NN>>>(sc, qkv + 2 * BSD, out,
                                       SEQ, DIM, SEQ,
                                       (long long)SEQ * SEQ, (long long)SEQ * DIM,
                                       (long long)SEQ * DIM, 1.0f);
    }
}

// round 10
// speedup vs baseline: 1.0384x; 1.0384x over previous
#include <cuda_runtime.h>
#include <cuda_bf16.h>
#include <cstdint>

// Problem constants
static constexpr int BATCH = 8;
static constexpr int SEQ   = 2048;
static constexpr int DIM   = 768;
static constexpr long long BSD = (long long)BATCH * SEQ * DIM;

// Scratch (device globals: allocation-free per harness rules). 16B-aligned for cp.async.
__device__ __align__(16) float g_xtf[BATCH * SEQ * DIM];      // x, tf32-rounded
__device__ __align__(16) float g_wt[3 * DIM * DIM];           // W^T per slice, tf32-rounded
__device__ __align__(16) float g_qkv[3 * BATCH * SEQ * DIM];  // q|k|v (tf32-rounded)
__device__ __align__(16) float g_s[BATCH * SEQ * SEQ];        // scores / attn

__device__ __forceinline__ uint32_t f2tf32(float f) {
    uint32_t u;
    asm volatile("cvt.rna.tf32.f32 %0, %1;" : "=r"(u) : "f"(f));
    return u;
}
__device__ __forceinline__ float rna(float f) { return __uint_as_float(f2tf32(f)); }

__device__ __forceinline__ void mma_tf32(
    float& c0, float& c1, float& c2, float& c3,
    uint32_t a0, uint32_t a1, uint32_t a2, uint32_t a3,
    uint32_t b0, uint32_t b1)
{
    asm volatile(
        "mma.sync.aligned.m16n8k8.row.col.f32.tf32.tf32.f32 "
        "{%0,%1,%2,%3}, {%4,%5,%6,%7}, {%8,%9}, {%0,%1,%2,%3};\n"
        : "+f"(c0), "+f"(c1), "+f"(c2), "+f"(c3)
        : "r"(a0), "r"(a1), "r"(a2), "r"(a3), "r"(b0), "r"(b1));
}

__device__ __forceinline__ void ldmx4(uint32_t& r0, uint32_t& r1, uint32_t& r2, uint32_t& r3,
                                      uint32_t saddr)
{
    asm volatile("ldmatrix.sync.aligned.m8n8.x4.shared.b16 {%0,%1,%2,%3}, [%4];"
                 : "=r"(r0), "=r"(r1), "=r"(r2), "=r"(r3) : "r"(saddr));
}

__device__ __forceinline__ void cp16(void* smem_dst, const void* gsrc) {
    uint32_t sa = (uint32_t)__cvta_generic_to_shared(smem_dst);
    asm volatile("cp.async.cg.shared.global [%0], [%1], 16;\n" :: "r"(sa), "l"(gsrc));
}

// ---------------------------------------------------------------------------
// tf32 tensor-core GEMM, 3-stage cp.async pipeline: C = alpha * A @ B(^T)
// Inputs MUST already be tf32-rounded fp32 (no CVT in consumer loop).
//   A: [M,K] row-major; B: NT (BT=true) -> [N,K]; NN -> [K,N]; C: [M,N]
// CTA 128x128x32, 8 warps (2x4), warp tile 64x32, mma m16n8k8; 2 CTAs/SM.
//   As  [m][k]  stride 36 ; BsNT [n][k] stride 36 ; BsNN [k][n] stride 136
// R10: fragment loads via ldmatrix.m8n8.x4 (A always; B too when NT).
// Each x4 = one 16x8-tf32 fragment (4 regs): 4x fewer LDS scoreboard ops.
// Bank pattern: rows r hit banks (4r+koff)..+3 -> all 32 banks, conflict-free.
// ---------------------------------------------------------------------------
#define BM 128
#define BN 128
#define BK 32
#define STAGES 3

static constexpr int AS_STRIDE = BK + 4;                 // 36
static constexpr int ASZ = BM * AS_STRIDE;               // floats per A stage
template <bool BT> struct BDims {
    static constexpr int STRIDE = BT ? (BK + 4) : (BN + 8);
    static constexpr int SZ     = BT ? (BN * (BK + 4)) : (BK * (BN + 8));
};

template <bool BT, bool ROUND>
__global__ __launch_bounds__(256, 2) void mma_gemm(
    const float* __restrict__ Ab, const float* __restrict__ Bb,
    float* __restrict__ Cb,
    int M, int N, int K,
    long long sA, long long sB, long long sC, float alpha)
{
    constexpr int BS_STRIDE = BDims<BT>::STRIDE;
    constexpr int BSZ       = BDims<BT>::SZ;

    const float* A = Ab + (long long)blockIdx.z * sA;
    const float* B = Bb + (long long)blockIdx.z * sB;
    float*       C = Cb + (long long)blockIdx.z * sC;

    extern __shared__ float smem[];
    float* AsBase = smem;
    float* BsBase = smem + STAGES * ASZ;

    const int tid  = threadIdx.x;
    const int warp = tid >> 5;
    const int lane = tid & 31;
    const int gid  = lane >> 2;   // 0..7
    const int tig  = lane & 3;    // 0..3
    const int wm   = (warp >> 2) * 64;
    const int wn   = (warp & 3) * 32;
    const int row0 = blockIdx.y * BM;
    const int col0 = blockIdx.x * BN;

    // ldmatrix per-lane byte offsets (within a stage buffer)
    //   A (and NT B): matrices (rows r..r+15) x (col koff, koff+4)
    //   lanes 0-15 -> col +0, rows +lane; lanes 16-31 -> col +4 words (+16B)
    const uint32_t laneAOff = (uint32_t)((lane & 15) * AS_STRIDE * 4 + (lane & 16));
    //   B NT: lanes 0-7 row+l, col 0 | 8-15 row+l, col+4 | 16-23 row+8+l, col 0 | 24-31 row+8+l, col+4
    const uint32_t laneBOff = (uint32_t)(((lane & 7) + ((lane & 16) >> 1)) * BS_STRIDE * 4
                                         + (lane & 8) * 2);

    float c[4][4][4];
#pragma unroll
    for (int i = 0; i < 4; i++)
#pragma unroll
        for (int j = 0; j < 4; j++)
#pragma unroll
            for (int r = 0; r < 4; r++) c[i][j][r] = 0.f;

    const int aR = tid >> 3;            // 0..31 (+32/pass), 16B along k
    const int aC = (tid & 7) * 4;
    const int bR = tid >> 5;            // 0..7 (+8/pass), 16B along n (NN)
    const int bC = (tid & 31) * 4;

    auto load_tile = [&](int stage, int kt) {
        float* As = AsBase + stage * ASZ;
        float* Bs = BsBase + stage * BSZ;
#pragma unroll
        for (int p = 0; p < 4; p++) {
            int r = aR + p * 32;
            cp16(&As[r * AS_STRIDE + aC], A + (long long)(row0 + r) * K + kt + aC);
        }
        if (BT) {
#pragma unroll
            for (int p = 0; p < 4; p++) {
                int r = aR + p * 32;
                cp16(&Bs[r * BS_STRIDE + aC], B + (long long)(col0 + r) * K + kt + aC);
            }
        } else {
#pragma unroll
            for (int p = 0; p < 4; p++) {
                int r = bR + p * 8;
                cp16(&Bs[r * BS_STRIDE + bC], B + (long long)(kt + r) * N + col0 + bC);
            }
        }
    };

    const int T = K / BK;
    load_tile(0, 0);
    asm volatile("cp.async.commit_group;\n");
    load_tile(1, BK);
    asm volatile("cp.async.commit_group;\n");

    for (int t = 0; t < T; t++) {
        // R8 schedule: issue tile t+2's loads BEFORE blocking.
        int nt = t + 2;
        if (nt < T) load_tile(nt % STAGES, nt * BK);
        asm volatile("cp.async.commit_group;\n");
        asm volatile("cp.async.wait_group 2;\n");   // tile t complete
        __syncthreads();

        float* AsF = AsBase + (t % STAGES) * ASZ;
        float* BsF = BsBase + (t % STAGES) * BSZ;
        const uint32_t asAddr = (uint32_t)__cvta_generic_to_shared(AsF) + laneAOff;
        const uint32_t bsAddrNT = (uint32_t)__cvta_generic_to_shared(BsF) + laneBOff;
        const uint32_t* Bs = (const uint32_t*)BsF;

#pragma unroll
        for (int ks = 0; ks < BK; ks += 8) {
            uint32_t a[4][4];
#pragma unroll
            for (int i = 0; i < 4; i++)
                ldmx4(a[i][0], a[i][1], a[i][2], a[i][3],
                      asAddr + (uint32_t)(((wm + 16 * i) * AS_STRIDE + ks) * 4));
            uint32_t b[4][2];
            if (BT) {
#pragma unroll
                for (int jp = 0; jp < 2; jp++)
                    ldmx4(b[2 * jp][0], b[2 * jp][1], b[2 * jp + 1][0], b[2 * jp + 1][1],
                          bsAddrNT + (uint32_t)(((wn + 16 * jp) * BS_STRIDE + ks) * 4));
            } else {
#pragma unroll
                for (int j = 0; j < 4; j++) {
                    int n = wn + 8 * j + gid;
                    b[j][0] = Bs[(ks + tig) * BS_STRIDE + n];
                    b[j][1] = Bs[(ks + tig + 4) * BS_STRIDE + n];
                }
            }
#pragma unroll
            for (int i = 0; i < 4; i++)
#pragma unroll
                for (int j = 0; j < 4; j++)
                    mma_tf32(c[i][j][0], c[i][j][1], c[i][j][2], c[i][j][3],
                             a[i][0], a[i][1], a[i][2], a[i][3],
                             b[j][0], b[j][1]);
        }
        __syncthreads();
    }

#pragma unroll
    for (int i = 0; i < 4; i++) {
        int rowA = row0 + wm + 16 * i + gid;
#pragma unroll
        for (int j = 0; j < 4; j++) {
            int col = col0 + wn + 8 * j + 2 * tig;
            float f0 = c[i][j][0] * alpha, f1 = c[i][j][1] * alpha;
            float f2 = c[i][j][2] * alpha, f3 = c[i][j][3] * alpha;
            if (ROUND) { f0 = rna(f0); f1 = rna(f1); f2 = rna(f2); f3 = rna(f3); }
            *(float2*)(C + (long long)rowA * N + col) = make_float2(f0, f1);
            *(float2*)(C + (long long)(rowA + 8) * N + col) = make_float2(f2, f3);
        }
    }
}

// ---------------------------------------------------------------------------
// Elementwise tf32 rounding (prep)
// ---------------------------------------------------------------------------
__global__ __launch_bounds__(256) void cvt_rna_kernel(
    const float* __restrict__ in, float* __restrict__ out)
{
    int i = (blockIdx.x * 256 + threadIdx.x) * 4;
    float4 v = *(const float4*)(in + i);
    v.x = rna(v.x); v.y = rna(v.y); v.z = rna(v.z); v.w = rna(v.w);
    *(float4*)(out + i) = v;
}

// out[z][c][r] = rna(in[z][r][c]); in: R x C per z slice
__global__ __launch_bounds__(256) void transpose_cvt(
    const float* __restrict__ in, float* __restrict__ out,
    int R, int Ccols, long long zStride)
{
    __shared__ float t[32][33];
    const float* inz  = in  + blockIdx.z * zStride;
    float*       outz = out + blockIdx.z * zStride;
    const int r0 = blockIdx.y * 32;
    const int c0 = blockIdx.x * 32;
    const int tx = threadIdx.x & 31;
    const int ty = threadIdx.x >> 5;   // 0..7
#pragma unroll
    for (int k = 0; k < 4; k++)
        t[ty + k * 8][tx] = inz[(long long)(r0 + ty + k * 8) * Ccols + c0 + tx];
    __syncthreads();
#pragma unroll
    for (int k = 0; k < 4; k++)
        outz[(long long)(c0 + ty + k * 8) * R + r0 + tx] = rna(t[tx][ty + k * 8]);
}

// ---------------------------------------------------------------------------
// Row softmax over 2048 columns; float4 I/O; writes tf32-rounded probabilities
// ---------------------------------------------------------------------------
__global__ __launch_bounds__(256) void softmax2048(float* __restrict__ S)
{
    float4* row4 = (float4*)(S + (long long)blockIdx.x * SEQ);
    const int tid = threadIdx.x;

    float4 va = row4[tid];
    float4 vb = row4[tid + 256];
    float x[8] = {va.x, va.y, va.z, va.w, vb.x, vb.y, vb.z, vb.w};

    float m = x[0];
#pragma unroll
    for (int i = 1; i < 8; i++) m = fmaxf(m, x[i]);
#pragma unroll
    for (int o = 16; o > 0; o >>= 1)
        m = fmaxf(m, __shfl_xor_sync(0xffffffffu, m, o));

    __shared__ float red[8];
    if ((tid & 31) == 0) red[tid >> 5] = m;
    __syncthreads();
    float mAll = red[0];
#pragma unroll
    for (int i = 1; i < 8; i++) mAll = fmaxf(mAll, red[i]);
    __syncthreads();

    float s = 0.f;
#pragma unroll
    for (int i = 0; i < 8; i++) {
        x[i] = __expf(x[i] - mAll);
        s += x[i];
    }
#pragma unroll
    for (int o = 16; o > 0; o >>= 1)
        s += __shfl_xor_sync(0xffffffffu, s, o);
    if ((tid & 31) == 0) red[tid >> 5] = s;
    __syncthreads();
    float tot = 0.f;
#pragma unroll
    for (int i = 0; i < 8; i++) tot += red[i];

    const float inv = 1.f / tot;
#pragma unroll
    for (int i = 0; i < 8; i++) x[i] = rna(x[i] * inv);
    row4[tid]       = make_float4(x[0], x[1], x[2], x[3]);
    row4[tid + 256] = make_float4(x[4], x[5], x[6], x[7]);
}

// ---------------------------------------------------------------------------
// Launch
// ---------------------------------------------------------------------------
extern "C" void kernel_launch(void* const* d_in, const int* in_sizes, int n_in,
                              void* d_out, int out_size)
{
    const float* x = (const float*)d_in[0];   // [8, 2048, 768]
    const float* w = (const float*)d_in[1];   // [3, 768, 768]
    float* out     = (float*)d_out;           // [8, 2048, 768]

    float *xtf, *wt, *qkv, *sc;
    cudaGetSymbolAddress((void**)&xtf, g_xtf);
    cudaGetSymbolAddress((void**)&wt,  g_wt);
    cudaGetSymbolAddress((void**)&qkv, g_qkv);
    cudaGetSymbolAddress((void**)&sc,  g_s);

    const float INV_SCALE = 0.125f;  // 1 / sqrt(64)

    constexpr int SMEM_NN = STAGES * (ASZ + BDims<false>::SZ) * 4;  // 107,520 B
    constexpr int SMEM_NT = STAGES * (ASZ + BDims<true>::SZ) * 4;   // 110,592 B

    cudaFuncSetAttribute(mma_gemm<true, true>,
                         cudaFuncAttributeMaxDynamicSharedMemorySize, SMEM_NT);
    cudaFuncSetAttribute(mma_gemm<true, false>,
                         cudaFuncAttributeMaxDynamicSharedMemorySize, SMEM_NT);
    cudaFuncSetAttribute(mma_gemm<false, false>,
                         cudaFuncAttributeMaxDynamicSharedMemorySize, SMEM_NN);

    // 0) x -> tf32-rounded; W -> W^T tf32-rounded (QKV becomes NT for ldmatrix)
    cvt_rna_kernel<<<(BATCH * SEQ * DIM) / 1024, 256>>>(x, xtf);
    transpose_cvt<<<dim3(DIM / 32, DIM / 32, 3), 256>>>(
        w, wt, DIM, DIM, (long long)DIM * DIM);

    // 1) QKV (NT): qkv[z] = xtf @ wt[z]^T; outputs tf32-rounded
    {
        dim3 grid(DIM / BN, (BATCH * SEQ) / BM, 3);
        mma_gemm<true, true><<<grid, 256, SMEM_NT>>>(xtf, wt, qkv,
                                       BATCH * SEQ, DIM, DIM,
                                       0LL, (long long)DIM * DIM, BSD, 1.0f);
    }

    // 2) scores = Q @ K^T / 8  (NT, batched over 8)
    {
        dim3 grid(SEQ / BN, SEQ / BM, BATCH);
        mma_gemm<true, false><<<grid, 256, SMEM_NT>>>(qkv, qkv + BSD, sc,
                                      SEQ, SEQ, DIM,
                                      (long long)SEQ * DIM, (long long)SEQ * DIM,
                                      (long long)SEQ * SEQ, INV_SCALE);
    }

    // 3) softmax over last dim; writes tf32-rounded attn
    softmax2048<<<BATCH * SEQ, 256>>>(sc);

    // 4) out = attn @ V  (NN, batched over 8; ldmatrix on A only)
    {
        dim3 grid(DIM / BN, SEQ / BM, BATCH);
        mma_gemm<false, false><<<grid, 256, SMEM_NN>>>(sc, qkv + 2 * BSD, out,
                                       SEQ, DIM, SEQ,
                                       (long long)SEQ * SEQ, (long long)SEQ * DIM,
                                       (long long)SEQ * DIM, 1.0f);
    }
}

// round 11
// speedup vs baseline: 1.1638x; 1.1208x over previous
#include <cuda_runtime.h>
#include <cuda_bf16.h>
#include <cstdint>

// Problem constants
static constexpr int BATCH = 8;
static constexpr int SEQ   = 2048;
static constexpr int DIM   = 768;
static constexpr long long BSD = (long long)BATCH * SEQ * DIM;

// Scratch (device globals: allocation-free per harness rules). 16B-aligned for cp.async.
__device__ __align__(16) float g_xtf[BATCH * SEQ * DIM];      // x, tf32-rounded
__device__ __align__(16) float g_wt[3 * DIM * DIM];           // W^T per slice, tf32-rounded
__device__ __align__(16) float g_qkv[3 * BATCH * SEQ * DIM];  // q|k|v (tf32-rounded)
__device__ __align__(16) float g_s[BATCH * SEQ * SEQ];        // scores / attn

__device__ __forceinline__ uint32_t f2tf32(float f) {
    uint32_t u;
    asm volatile("cvt.rna.tf32.f32 %0, %1;" : "=r"(u) : "f"(f));
    return u;
}
__device__ __forceinline__ float rna(float f) { return __uint_as_float(f2tf32(f)); }

__device__ __forceinline__ void mma_tf32(
    float& c0, float& c1, float& c2, float& c3,
    uint32_t a0, uint32_t a1, uint32_t a2, uint32_t a3,
    uint32_t b0, uint32_t b1)
{
    asm volatile(
        "mma.sync.aligned.m16n8k8.row.col.f32.tf32.tf32.f32 "
        "{%0,%1,%2,%3}, {%4,%5,%6,%7}, {%8,%9}, {%0,%1,%2,%3};\n"
        : "+f"(c0), "+f"(c1), "+f"(c2), "+f"(c3)
        : "r"(a0), "r"(a1), "r"(a2), "r"(a3), "r"(b0), "r"(b1));
}

__device__ __forceinline__ void ldmx4(uint32_t& r0, uint32_t& r1, uint32_t& r2, uint32_t& r3,
                                      uint32_t saddr)
{
    asm volatile("ldmatrix.sync.aligned.m8n8.x4.shared.b16 {%0,%1,%2,%3}, [%4];"
                 : "=r"(r0), "=r"(r1), "=r"(r2), "=r"(r3) : "r"(saddr));
}

__device__ __forceinline__ void cp16(void* smem_dst, const void* gsrc) {
    uint32_t sa = (uint32_t)__cvta_generic_to_shared(smem_dst);
    asm volatile("cp.async.cg.shared.global [%0], [%1], 16;\n" :: "r"(sa), "l"(gsrc));
}

// ---- mbarrier helpers ----
__device__ __forceinline__ void mbar_init(uint32_t a, uint32_t cnt) {
    asm volatile("mbarrier.init.shared.b64 [%0], %1;" :: "r"(a), "r"(cnt) : "memory");
}
__device__ __forceinline__ void mbar_arrive(uint32_t a) {
    asm volatile("mbarrier.arrive.shared.b64 _, [%0];" :: "r"(a) : "memory");
}
// Arrive on mbar when all of this thread's prior cp.asyncs have completed.
// .noinc: expected count is NOT bumped (init count covers all 256 threads).
__device__ __forceinline__ void cpasync_mbar_arrive(uint32_t a) {
    asm volatile("cp.async.mbarrier.arrive.noinc.shared.b64 [%0];" :: "r"(a) : "memory");
}
__device__ __forceinline__ void mbar_wait(uint32_t a, uint32_t parity) {
    asm volatile(
        "{\n\t.reg .pred P;\n"
        "WL_%=:\n\t"
        "mbarrier.try_wait.parity.acquire.cta.shared::cta.b64 P, [%0], %1, 0x989680;\n\t"
        "@P bra.uni WD_%=;\n\t"
        "bra.uni WL_%=;\n"
        "WD_%=:\n\t}"
        :: "r"(a), "r"(parity) : "memory");
}

// ---------------------------------------------------------------------------
// tf32 tensor-core GEMM, 3-stage cp.async pipeline with PER-STAGE MBARRIERS.
// C = alpha * A @ B(^T); inputs already tf32-rounded.
//   A: [M,K] row-major; B: NT (BT=true) -> [N,K]; NN -> [K,N]; C: [M,N]
// CTA 128x128x32, 8 warps (2x4), warp tile 64x32, ldmatrix + mma m16n8k8;
// 2 CTAs/SM.   As [m][k] s36 ; BsNT [n][k] s36 ; BsNN [k][n] s136
// R11: NO __syncthreads in the main loop. full[s]: 256 cp.async arrivals;
// empty[s]: 8 per-warp arrivals. Warps drift up to 3 stages apart, so
// ldmatrix and MMA phases interleave across warps instead of lockstep.
// ---------------------------------------------------------------------------
#define BM 128
#define BN 128
#define BK 32
#define STAGES 3

static constexpr int AS_STRIDE = BK + 4;                 // 36
static constexpr int ASZ = BM * AS_STRIDE;               // floats per A stage
static constexpr int MBAR_FLOATS = 32;                   // 128 B for 3x(full,empty)
template <bool BT> struct BDims {
    static constexpr int STRIDE = BT ? (BK + 4) : (BN + 8);
    static constexpr int SZ     = BT ? (BN * (BK + 4)) : (BK * (BN + 8));
};

template <bool BT, bool ROUND>
__global__ __launch_bounds__(256, 2) void mma_gemm(
    const float* __restrict__ Ab, const float* __restrict__ Bb,
    float* __restrict__ Cb,
    int M, int N, int K,
    long long sA, long long sB, long long sC, float alpha)
{
    constexpr int BS_STRIDE = BDims<BT>::STRIDE;
    constexpr int BSZ       = BDims<BT>::SZ;

    const float* A = Ab + (long long)blockIdx.z * sA;
    const float* B = Bb + (long long)blockIdx.z * sB;
    float*       C = Cb + (long long)blockIdx.z * sC;

    extern __shared__ float smem[];
    const uint32_t mb = (uint32_t)__cvta_generic_to_shared(smem);  // mbar area
    float* AsBase = smem + MBAR_FLOATS;
    float* BsBase = AsBase + STAGES * ASZ;

    const int tid  = threadIdx.x;
    const int warp = tid >> 5;
    const int lane = tid & 31;
    const int gid  = lane >> 2;   // 0..7
    const int tig  = lane & 3;    // 0..3
    const int wm   = (warp >> 2) * 64;
    const int wn   = (warp & 3) * 32;
    const int row0 = blockIdx.y * BM;
    const int col0 = blockIdx.x * BN;

    // mbarrier addresses: full[s] = mb + s*16, empty[s] = mb + s*16 + 8
    if (tid == 0) {
#pragma unroll
        for (int s = 0; s < STAGES; s++) {
            mbar_init(mb + s * 16, 256);    // full: one cp.async arrive per thread
            mbar_init(mb + s * 16 + 8, 8);  // empty: one arrive per warp
        }
    }
    __syncthreads();
    // Pre-arm empties: phase 0 of each empty completes -> producers may fill.
    if (lane == 0) {
#pragma unroll
        for (int s = 0; s < STAGES; s++) mbar_arrive(mb + s * 16 + 8);
    }

    // ldmatrix per-lane byte offsets (within a stage buffer) — verified R10
    const uint32_t laneAOff = (uint32_t)((lane & 15) * AS_STRIDE * 4 + (lane & 16));
    const uint32_t laneBOff = (uint32_t)(((lane & 7) + ((lane & 16) >> 1)) * BS_STRIDE * 4
                                         + (lane & 8) * 2);

    float c[4][4][4];
#pragma unroll
    for (int i = 0; i < 4; i++)
#pragma unroll
        for (int j = 0; j < 4; j++)
#pragma unroll
            for (int r = 0; r < 4; r++) c[i][j][r] = 0.f;

    const int aR = tid >> 3;            // 0..31 (+32/pass), 16B along k
    const int aC = (tid & 7) * 4;
    const int bR = tid >> 5;            // 0..7 (+8/pass), 16B along n (NN)
    const int bC = (tid & 31) * 4;

    auto load_tile = [&](int stage, int kt) {
        float* As = AsBase + stage * ASZ;
        float* Bs = BsBase + stage * BSZ;
#pragma unroll
        for (int p = 0; p < 4; p++) {
            int r = aR + p * 32;
            cp16(&As[r * AS_STRIDE + aC], A + (long long)(row0 + r) * K + kt + aC);
        }
        if (BT) {
#pragma unroll
            for (int p = 0; p < 4; p++) {
                int r = aR + p * 32;
                cp16(&Bs[r * BS_STRIDE + aC], B + (long long)(col0 + r) * K + kt + aC);
            }
        } else {
#pragma unroll
            for (int p = 0; p < 4; p++) {
                int r = bR + p * 8;
                cp16(&Bs[r * BS_STRIDE + bC], B + (long long)(kt + r) * N + col0 + bC);
            }
        }
    };

    const int T = K / BK;

    // Producer cursor (per thread)
    int ps = 0, pp = 0;
    // Prologue: fill up to STAGES tiles (empty phase 0 already complete).
#pragma unroll
    for (int i = 0; i < STAGES; i++) {
        if (i < T) {
            mbar_wait(mb + ps * 16 + 8, pp);
            load_tile(ps, i * BK);
            cpasync_mbar_arrive(mb + ps * 16);
            if (++ps == STAGES) { ps = 0; pp ^= 1; }
        }
    }

    // Consumer cursor (per warp, tracked per thread)
    int cs = 0, cph = 0;
    for (int t = 0; t < T; t++) {
        mbar_wait(mb + cs * 16, cph);   // stage cs tile ready (acquire)

        float* AsF = AsBase + cs * ASZ;
        float* BsF = BsBase + cs * BSZ;
        const uint32_t asAddr = (uint32_t)__cvta_generic_to_shared(AsF) + laneAOff;
        const uint32_t bsAddrNT = (uint32_t)__cvta_generic_to_shared(BsF) + laneBOff;
        const uint32_t* Bs = (const uint32_t*)BsF;

#pragma unroll
        for (int ks = 0; ks < BK; ks += 8) {
            uint32_t a[4][4];
#pragma unroll
            for (int i = 0; i < 4; i++)
                ldmx4(a[i][0], a[i][1], a[i][2], a[i][3],
                      asAddr + (uint32_t)(((wm + 16 * i) * AS_STRIDE + ks) * 4));
            uint32_t b[4][2];
            if (BT) {
#pragma unroll
                for (int jp = 0; jp < 2; jp++)
                    ldmx4(b[2 * jp][0], b[2 * jp][1], b[2 * jp + 1][0], b[2 * jp + 1][1],
                          bsAddrNT + (uint32_t)(((wn + 16 * jp) * BS_STRIDE + ks) * 4));
            } else {
#pragma unroll
                for (int j = 0; j < 4; j++) {
                    int n = wn + 8 * j + gid;
                    b[j][0] = Bs[(ks + tig) * BS_STRIDE + n];
                    b[j][1] = Bs[(ks + tig + 4) * BS_STRIDE + n];
                }
            }
#pragma unroll
            for (int i = 0; i < 4; i++)
#pragma unroll
                for (int j = 0; j < 4; j++)
                    mma_tf32(c[i][j][0], c[i][j][1], c[i][j][2], c[i][j][3],
                             a[i][0], a[i][1], a[i][2], a[i][3],
                             b[j][0], b[j][1]);
        }

        // This warp is done reading stage cs.
        if (lane == 0) mbar_arrive(mb + cs * 16 + 8);
        if (++cs == STAGES) { cs = 0; cph ^= 1; }

        // Produce tile t+STAGES into the stage being freed.
        int nt = t + STAGES;
        if (nt < T) {
            mbar_wait(mb + ps * 16 + 8, pp);   // all 8 warps done with that stage
            load_tile(ps, nt * BK);
            cpasync_mbar_arrive(mb + ps * 16);
            if (++ps == STAGES) { ps = 0; pp ^= 1; }
        }
    }

#pragma unroll
    for (int i = 0; i < 4; i++) {
        int rowA = row0 + wm + 16 * i + gid;
#pragma unroll
        for (int j = 0; j < 4; j++) {
            int col = col0 + wn + 8 * j + 2 * tig;
            float f0 = c[i][j][0] * alpha, f1 = c[i][j][1] * alpha;
            float f2 = c[i][j][2] * alpha, f3 = c[i][j][3] * alpha;
            if (ROUND) { f0 = rna(f0); f1 = rna(f1); f2 = rna(f2); f3 = rna(f3); }
            *(float2*)(C + (long long)rowA * N + col) = make_float2(f0, f1);
            *(float2*)(C + (long long)(rowA + 8) * N + col) = make_float2(f2, f3);
        }
    }
}

// ---------------------------------------------------------------------------
// Elementwise tf32 rounding (prep)
// ---------------------------------------------------------------------------
__global__ __launch_bounds__(256) void cvt_rna_kernel(
    const float* __restrict__ in, float* __restrict__ out)
{
    int i = (blockIdx.x * 256 + threadIdx.x) * 4;
    float4 v = *(const float4*)(in + i);
    v.x = rna(v.x); v.y = rna(v.y); v.z = rna(v.z); v.w = rna(v.w);
    *(float4*)(out + i) = v;
}

// out[z][c][r] = rna(in[z][r][c]); in: R x C per z slice
__global__ __launch_bounds__(256) void transpose_cvt(
    const float* __restrict__ in, float* __restrict__ out,
    int R, int Ccols, long long zStride)
{
    __shared__ float t[32][33];
    const float* inz  = in  + blockIdx.z * zStride;
    float*       outz = out + blockIdx.z * zStride;
    const int r0 = blockIdx.y * 32;
    const int c0 = blockIdx.x * 32;
    const int tx = threadIdx.x & 31;
    const int ty = threadIdx.x >> 5;   // 0..7
#pragma unroll
    for (int k = 0; k < 4; k++)
        t[ty + k * 8][tx] = inz[(long long)(r0 + ty + k * 8) * Ccols + c0 + tx];
    __syncthreads();
#pragma unroll
    for (int k = 0; k < 4; k++)
        outz[(long long)(c0 + ty + k * 8) * R + r0 + tx] = rna(t[tx][ty + k * 8]);
}

// ---------------------------------------------------------------------------
// Row softmax over 2048 columns; float4 I/O; writes tf32-rounded probabilities
// ---------------------------------------------------------------------------
__global__ __launch_bounds__(256) void softmax2048(float* __restrict__ S)
{
    float4* row4 = (float4*)(S + (long long)blockIdx.x * SEQ);
    const int tid = threadIdx.x;

    float4 va = row4[tid];
    float4 vb = row4[tid + 256];
    float x[8] = {va.x, va.y, va.z, va.w, vb.x, vb.y, vb.z, vb.w};

    float m = x[0];
#pragma unroll
    for (int i = 1; i < 8; i++) m = fmaxf(m, x[i]);
#pragma unroll
    for (int o = 16; o > 0; o >>= 1)
        m = fmaxf(m, __shfl_xor_sync(0xffffffffu, m, o));

    __shared__ float red[8];
    if ((tid & 31) == 0) red[tid >> 5] = m;
    __syncthreads();
    float mAll = red[0];
#pragma unroll
    for (int i = 1; i < 8; i++) mAll = fmaxf(mAll, red[i]);
    __syncthreads();

    float s = 0.f;
#pragma unroll
    for (int i = 0; i < 8; i++) {
        x[i] = __expf(x[i] - mAll);
        s += x[i];
    }
#pragma unroll
    for (int o = 16; o > 0; o >>= 1)
        s += __shfl_xor_sync(0xffffffffu, s, o);
    if ((tid & 31) == 0) red[tid >> 5] = s;
    __syncthreads();
    float tot = 0.f;
#pragma unroll
    for (int i = 0; i < 8; i++) tot += red[i];

    const float inv = 1.f / tot;
#pragma unroll
    for (int i = 0; i < 8; i++) x[i] = rna(x[i] * inv);
    row4[tid]       = make_float4(x[0], x[1], x[2], x[3]);
    row4[tid + 256] = make_float4(x[4], x[5], x[6], x[7]);
}

// ---------------------------------------------------------------------------
// Launch
// ---------------------------------------------------------------------------
extern "C" void kernel_launch(void* const* d_in, const int* in_sizes, int n_in,
                              void* d_out, int out_size)
{
    const float* x = (const float*)d_in[0];   // [8, 2048, 768]
    const float* w = (const float*)d_in[1];   // [3, 768, 768]
    float* out     = (float*)d_out;           // [8, 2048, 768]

    float *xtf, *wt, *qkv, *sc;
    cudaGetSymbolAddress((void**)&xtf, g_xtf);
    cudaGetSymbolAddress((void**)&wt,  g_wt);
    cudaGetSymbolAddress((void**)&qkv, g_qkv);
    cudaGetSymbolAddress((void**)&sc,  g_s);

    const float INV_SCALE = 0.125f;  // 1 / sqrt(64)

    constexpr int SMEM_NN = (MBAR_FLOATS + STAGES * (ASZ + BDims<false>::SZ)) * 4;
    constexpr int SMEM_NT = (MBAR_FLOATS + STAGES * (ASZ + BDims<true>::SZ)) * 4;

    cudaFuncSetAttribute(mma_gemm<true, true>,
                         cudaFuncAttributeMaxDynamicSharedMemorySize, SMEM_NT);
    cudaFuncSetAttribute(mma_gemm<true, false>,
                         cudaFuncAttributeMaxDynamicSharedMemorySize, SMEM_NT);
    cudaFuncSetAttribute(mma_gemm<false, false>,
                         cudaFuncAttributeMaxDynamicSharedMemorySize, SMEM_NN);

    // 0) x -> tf32-rounded; W -> W^T tf32-rounded (QKV is NT for ldmatrix)
    cvt_rna_kernel<<<(BATCH * SEQ * DIM) / 1024, 256>>>(x, xtf);
    transpose_cvt<<<dim3(DIM / 32, DIM / 32, 3), 256>>>(
        w, wt, DIM, DIM, (long long)DIM * DIM);

    // 1) QKV (NT): qkv[z] = xtf @ wt[z]^T; outputs tf32-rounded
    {
        dim3 grid(DIM / BN, (BATCH * SEQ) / BM, 3);
        mma_gemm<true, true><<<grid, 256, SMEM_NT>>>(xtf, wt, qkv,
                                       BATCH * SEQ, DIM, DIM,
                                       0LL, (long long)DIM * DIM, BSD, 1.0f);
    }

    // 2) scores = Q @ K^T / 8  (NT, batched over 8)
    {
        dim3 grid(SEQ / BN, SEQ / BM, BATCH);
        mma_gemm<true, false><<<grid, 256, SMEM_NT>>>(qkv, qkv + BSD, sc,
                                      SEQ, SEQ, DIM,
                                      (long long)SEQ * DIM, (long long)SEQ * DIM,
                                      (long long)SEQ * SEQ, INV_SCALE);
    }

    // 3) softmax over last dim; writes tf32-rounded attn
    softmax2048<<<BATCH * SEQ, 256>>>(sc);

    // 4) out = attn @ V  (NN, batched over 8; ldmatrix on A only)
    {
        dim3 grid(DIM / BN, SEQ / BM, BATCH);
        mma_gemm<false, false><<<grid, 256, SMEM_NN>>>(sc, qkv + 2 * BSD, out,
                                       SEQ, DIM, SEQ,
                                       (long long)SEQ * SEQ, (long long)SEQ * DIM,
                                       (long long)SEQ * DIM, 1.0f);
    }
}